// round 2
// baseline (speedup 1.0000x reference)
#include <cuda_runtime.h>
#include <cuda_bf16.h>
#include <math.h>

// ---------------------------------------------------------------------------
// Problem constants
// ---------------------------------------------------------------------------
#define N_NODES 50000
#define N_EDGES 800000
#define IN_DIM  128
#define HID     64
#define HEADS   4
#define H1DIM   (HEADS * HID)   // 256
#define OUT_DIM 64
#define NEG_SLOPE 0.2f

// ---------------------------------------------------------------------------
// Device scratch (static device globals; no runtime allocation)
// ---------------------------------------------------------------------------
__device__ float g_h1[(size_t)N_NODES * H1DIM];   // x @ W1          (51.2 MB)
__device__ float g_hh[(size_t)N_NODES * H1DIM];   // elu(agg1 + b1)  (51.2 MB)
__device__ float g_h2[(size_t)N_NODES * OUT_DIM]; // hh @ W2         (12.8 MB)
__device__ float g_as1[N_NODES * HEADS];
__device__ float g_ad1[N_NODES * HEADS];
__device__ float g_as2[N_NODES];
__device__ float g_ad2[N_NODES];
__device__ int   g_deg[N_NODES];
__device__ int   g_rowptr[N_NODES + 1];
__device__ int   g_cursor[N_NODES];
__device__ int   g_esrc[N_EDGES];                 // src node per CSR slot

// ---------------------------------------------------------------------------
// CSR build (edge_index is int32: JAX x64 is disabled by default, so the
// reference's "int64" randint is actually int32 on the wire)
// ---------------------------------------------------------------------------
__global__ void k_zero_deg() {
    int i = blockIdx.x * blockDim.x + threadIdx.x;
    if (i < N_NODES) g_deg[i] = 0;
}

__global__ void k_hist(const int* __restrict__ ei) {
    int e = blockIdx.x * blockDim.x + threadIdx.x;
    if (e < N_EDGES) {
        int d = ei[N_EDGES + e];
        atomicAdd(&g_deg[d], 1);
    }
}

// single-block exclusive scan over 50000 ints (perf-irrelevant)
__global__ void k_scan() {
    __shared__ int sums[1024];
    const int tid = threadIdx.x;
    const int CH = (N_NODES + 1023) / 1024;  // 49
    int start = tid * CH;
    int s = 0;
    for (int i = 0; i < CH; i++) {
        int g = start + i;
        if (g < N_NODES) s += g_deg[g];
    }
    sums[tid] = s;
    __syncthreads();
    for (int off = 1; off < 1024; off <<= 1) {
        int v = (tid >= off) ? sums[tid - off] : 0;
        __syncthreads();
        sums[tid] += v;
        __syncthreads();
    }
    int run = (tid == 0) ? 0 : sums[tid - 1];
    for (int i = 0; i < CH; i++) {
        int g = start + i;
        if (g < N_NODES) {
            g_rowptr[g] = run;
            g_cursor[g] = run;
            run += g_deg[g];
        }
    }
    if (tid == 1023) g_rowptr[N_NODES] = run;
}

__global__ void k_fill(const int* __restrict__ ei) {
    int e = blockIdx.x * blockDim.x + threadIdx.x;
    if (e < N_EDGES) {
        int s = ei[e];
        int d = ei[N_EDGES + e];
        int pos = atomicAdd(&g_cursor[d], 1);
        g_esrc[pos] = s;
    }
}

// ---------------------------------------------------------------------------
// SGEMM: C[M,NN] = A[M,K] @ B[K,NN]. Block tile 128x64, BK=16, 256 threads,
// per-thread micro tile 8x4.
// ---------------------------------------------------------------------------
#define BM 128
#define BN 64
#define BK 16

template <int K, int NN>
__device__ __forceinline__ void gemm_body(const float* __restrict__ A,
                                          const float* __restrict__ B,
                                          float* __restrict__ C, int M) {
    __shared__ __align__(16) float As[BK][BM + 4];
    __shared__ __align__(16) float Bs[BK][BN];
    const int tid  = threadIdx.x;
    const int row0 = blockIdx.y * BM;
    const int col0 = blockIdx.x * BN;
    const int ty = tid >> 4, tx = tid & 15;
    const int ar = tid >> 2, ac = (tid & 3) * 4;
    const int br = tid >> 4, bc = (tid & 15) * 4;

    float acc[8][4];
#pragma unroll
    for (int i = 0; i < 8; i++)
#pragma unroll
        for (int j = 0; j < 4; j++) acc[i][j] = 0.f;

    for (int k0 = 0; k0 < K; k0 += BK) {
#pragma unroll
        for (int h = 0; h < 2; h++) {
            int r = ar + h * 64;
            int gr = row0 + r;
            float4 v = make_float4(0.f, 0.f, 0.f, 0.f);
            if (gr < M) v = *(const float4*)(A + (size_t)gr * K + k0 + ac);
            As[ac + 0][r] = v.x; As[ac + 1][r] = v.y;
            As[ac + 2][r] = v.z; As[ac + 3][r] = v.w;
        }
        *(float4*)&Bs[br][bc] =
            *(const float4*)(B + (size_t)(k0 + br) * NN + col0 + bc);
        __syncthreads();
#pragma unroll
        for (int kk = 0; kk < BK; kk++) {
            float4 a0 = *(const float4*)&As[kk][ty * 8];
            float4 a1 = *(const float4*)&As[kk][ty * 8 + 4];
            float4 bb = *(const float4*)&Bs[kk][tx * 4];
            float av[8] = {a0.x, a0.y, a0.z, a0.w, a1.x, a1.y, a1.z, a1.w};
            float bv[4] = {bb.x, bb.y, bb.z, bb.w};
#pragma unroll
            for (int i = 0; i < 8; i++)
#pragma unroll
                for (int j = 0; j < 4; j++) acc[i][j] += av[i] * bv[j];
        }
        __syncthreads();
    }
#pragma unroll
    for (int i = 0; i < 8; i++) {
        int gr = row0 + ty * 8 + i;
        if (gr < M)
            *(float4*)(C + (size_t)gr * NN + col0 + tx * 4) =
                make_float4(acc[i][0], acc[i][1], acc[i][2], acc[i][3]);
    }
}

__global__ void __launch_bounds__(256) k_gemm1(const float* __restrict__ x,
                                               const float* __restrict__ W1) {
    gemm_body<IN_DIM, H1DIM>(x, W1, g_h1, N_NODES);
}

__global__ void __launch_bounds__(256) k_gemm2(const float* __restrict__ W2) {
    gemm_body<H1DIM, OUT_DIM>(g_hh, W2, g_h2, N_NODES);
}

// ---------------------------------------------------------------------------
// Attention-coefficient dots. Layer 1: warp per node, 256 dims, reduce within
// 8-lane (per-head) groups. Layer 2: warp per node, 64 dims, full reduce.
// ---------------------------------------------------------------------------
__global__ void k_adot1(const float* __restrict__ asrc,
                        const float* __restrict__ adst) {
    int warp = (blockIdx.x * blockDim.x + threadIdx.x) >> 5;
    if (warp >= N_NODES) return;
    int lane = threadIdx.x & 31;
    const float4* hp = (const float4*)(g_h1 + (size_t)warp * H1DIM + lane * 8);
    float4 h0 = hp[0], h1v = hp[1];
    const float4* sp = (const float4*)(asrc + lane * 8);
    float4 s0 = sp[0], s1 = sp[1];
    const float4* dp = (const float4*)(adst + lane * 8);
    float4 d0 = dp[0], d1 = dp[1];
    float ps = h0.x * s0.x + h0.y * s0.y + h0.z * s0.z + h0.w * s0.w +
               h1v.x * s1.x + h1v.y * s1.y + h1v.z * s1.z + h1v.w * s1.w;
    float pd = h0.x * d0.x + h0.y * d0.y + h0.z * d0.z + h0.w * d0.w +
               h1v.x * d1.x + h1v.y * d1.y + h1v.z * d1.z + h1v.w * d1.w;
    ps += __shfl_xor_sync(~0u, ps, 1);
    ps += __shfl_xor_sync(~0u, ps, 2);
    ps += __shfl_xor_sync(~0u, ps, 4);
    pd += __shfl_xor_sync(~0u, pd, 1);
    pd += __shfl_xor_sync(~0u, pd, 2);
    pd += __shfl_xor_sync(~0u, pd, 4);
    if ((lane & 7) == 0) {
        g_as1[warp * HEADS + (lane >> 3)] = ps;
        g_ad1[warp * HEADS + (lane >> 3)] = pd;
    }
}

__global__ void k_adot2(const float* __restrict__ asrc,
                        const float* __restrict__ adst) {
    int warp = (blockIdx.x * blockDim.x + threadIdx.x) >> 5;
    if (warp >= N_NODES) return;
    int lane = threadIdx.x & 31;
    float2 h = *(const float2*)(g_h2 + (size_t)warp * OUT_DIM + lane * 2);
    float2 s = *(const float2*)(asrc + lane * 2);
    float2 d = *(const float2*)(adst + lane * 2);
    float ps = h.x * s.x + h.y * s.y;
    float pd = h.x * d.x + h.y * d.y;
#pragma unroll
    for (int off = 16; off >= 1; off >>= 1) {
        ps += __shfl_xor_sync(~0u, ps, off);
        pd += __shfl_xor_sync(~0u, pd, off);
    }
    if (lane == 0) { g_as2[warp] = ps; g_ad2[warp] = pd; }
}

// ---------------------------------------------------------------------------
// Layer-1 aggregation: warp per destination node.
// Virtual edge list = [self] + CSR edges. Phase mapping for e/exp work:
// lane = slot(lane>>2, 8 edge-slots) x head(lane&3).
// Dim mapping for accumulation: lane owns dims [lane*8, lane*8+8), head=lane>>3.
// ---------------------------------------------------------------------------
__global__ void k_agg1(const float* __restrict__ b1) {
    int d = (blockIdx.x * blockDim.x + threadIdx.x) >> 5;
    if (d >= N_NODES) return;
    int lane = threadIdx.x & 31;
    int row  = g_rowptr[d];
    int tot  = g_rowptr[d + 1] - row + 1;     // +1 for the self-loop
    const int headA = lane & 3;               // phase head
    const int slotA = lane >> 2;              // phase edge slot (0..7)
    const int headB = lane >> 3;              // dim head

    const float ad_h = g_ad1[d * HEADS + headA];

    // ---- phase 1: per-head max --------------------------------------------
    float m = -INFINITY;
    for (int base = 0; base < tot; base += 8) {
        int idx = base + slotA;
        float e = -INFINITY;
        if (idx < tot) {
            int s = (idx == 0) ? d : g_esrc[row + idx - 1];
            float v = g_as1[s * HEADS + headA] + ad_h;
            e = v > 0.f ? v : NEG_SLOPE * v;
        }
        m = fmaxf(m, e);
    }
    m = fmaxf(m, __shfl_xor_sync(~0u, m, 4));
    m = fmaxf(m, __shfl_xor_sync(~0u, m, 8));
    m = fmaxf(m, __shfl_xor_sync(~0u, m, 16));  // now: max for head (lane&3)

    // ---- phase 2: exp-sum + weighted gather -------------------------------
    float ssum = 0.f;
    float acc[8];
#pragma unroll
    for (int j = 0; j < 8; j++) acc[j] = 0.f;

    for (int base = 0; base < tot; base += 8) {
        int idx = base + slotA;
        int s = d;
        float p = 0.f;
        if (idx < tot) {
            if (idx > 0) s = g_esrc[row + idx - 1];
            float v = g_as1[s * HEADS + headA] + ad_h;
            float e = v > 0.f ? v : NEG_SLOPE * v;
            p = __expf(e - m);
        }
        ssum += p;
        int lim = min(8, tot - base);
        for (int e2 = 0; e2 < lim; e2++) {
            float pe = __shfl_sync(~0u, p, e2 * 4 + headB);
            int   sn = __shfl_sync(~0u, s, e2 * 4);
            const float4* hp =
                (const float4*)(g_h1 + (size_t)sn * H1DIM + lane * 8);
            float4 v0 = hp[0], v1 = hp[1];
            acc[0] += pe * v0.x; acc[1] += pe * v0.y;
            acc[2] += pe * v0.z; acc[3] += pe * v0.w;
            acc[4] += pe * v1.x; acc[5] += pe * v1.y;
            acc[6] += pe * v1.z; acc[7] += pe * v1.w;
        }
    }
    ssum += __shfl_xor_sync(~0u, ssum, 4);
    ssum += __shfl_xor_sync(~0u, ssum, 8);
    ssum += __shfl_xor_sync(~0u, ssum, 16);     // den for head (lane&3)
    float den = __shfl_sync(~0u, ssum, headB);  // den for this lane's dim-head
    float inv = 1.f / den;

    float* o = g_hh + (size_t)d * H1DIM + lane * 8;
#pragma unroll
    for (int j = 0; j < 8; j++) {
        float v = acc[j] * inv + b1[lane * 8 + j];
        o[j] = v > 0.f ? v : expm1f(v);          // ELU
    }
}

// ---------------------------------------------------------------------------
// Layer-2 aggregation (1 head, 64 dims) fused with final fc: out[d] scalar.
// Phase: lane = edge slot (32 per chunk). Dims: lane owns 2 floats.
// ---------------------------------------------------------------------------
__global__ void k_agg2(const float* __restrict__ b2,
                       const float* __restrict__ fcw,
                       const float* __restrict__ fcb,
                       float* __restrict__ out) {
    int d = (blockIdx.x * blockDim.x + threadIdx.x) >> 5;
    if (d >= N_NODES) return;
    int lane = threadIdx.x & 31;
    int row  = g_rowptr[d];
    int tot  = g_rowptr[d + 1] - row + 1;
    const float ad = g_ad2[d];

    float m = -INFINITY;
    for (int base = 0; base < tot; base += 32) {
        int idx = base + lane;
        float e = -INFINITY;
        if (idx < tot) {
            int s = (idx == 0) ? d : g_esrc[row + idx - 1];
            float v = g_as2[s] + ad;
            e = v > 0.f ? v : NEG_SLOPE * v;
        }
        m = fmaxf(m, e);
    }
#pragma unroll
    for (int off = 16; off >= 1; off >>= 1)
        m = fmaxf(m, __shfl_xor_sync(~0u, m, off));

    float ssum = 0.f, a0 = 0.f, a1 = 0.f;
    for (int base = 0; base < tot; base += 32) {
        int idx = base + lane;
        int s = d;
        float p = 0.f;
        if (idx < tot) {
            if (idx > 0) s = g_esrc[row + idx - 1];
            float v = g_as2[s] + ad;
            float e = v > 0.f ? v : NEG_SLOPE * v;
            p = __expf(e - m);
        }
        ssum += p;
        int lim = min(32, tot - base);
        for (int e2 = 0; e2 < lim; e2++) {
            float pe = __shfl_sync(~0u, p, e2);
            int   sn = __shfl_sync(~0u, s, e2);
            float2 hv = *(const float2*)(g_h2 + (size_t)sn * OUT_DIM + lane * 2);
            a0 += pe * hv.x;
            a1 += pe * hv.y;
        }
    }
#pragma unroll
    for (int off = 16; off >= 1; off >>= 1)
        ssum += __shfl_xor_sync(~0u, ssum, off);
    float inv = 1.f / ssum;
    float v0 = a0 * inv + b2[lane * 2];
    float v1 = a1 * inv + b2[lane * 2 + 1];
    float part = v0 * fcw[lane * 2] + v1 * fcw[lane * 2 + 1];
#pragma unroll
    for (int off = 16; off >= 1; off >>= 1)
        part += __shfl_xor_sync(~0u, part, off);
    if (lane == 0) out[d] = part + fcb[0];
}

// ---------------------------------------------------------------------------
// Launch
// ---------------------------------------------------------------------------
extern "C" void kernel_launch(void* const* d_in, const int* in_sizes, int n_in,
                              void* d_out, int out_size) {
    const float* x      = (const float*)d_in[0];
    const int*   ei     = (const int*)d_in[1];     // int32 (JAX x64 disabled)
    const float* W1     = (const float*)d_in[2];
    const float* a_src1 = (const float*)d_in[3];
    const float* a_dst1 = (const float*)d_in[4];
    const float* b1     = (const float*)d_in[5];
    const float* W2     = (const float*)d_in[6];
    const float* a_src2 = (const float*)d_in[7];
    const float* a_dst2 = (const float*)d_in[8];
    const float* b2     = (const float*)d_in[9];
    const float* fc_w   = (const float*)d_in[10];
    const float* fc_b   = (const float*)d_in[11];
    float*       out    = (float*)d_out;

    // CSR build (dst-sorted incoming-edge lists; self-loops handled implicitly)
    k_zero_deg<<<(N_NODES + 255) / 256, 256>>>();
    k_hist<<<(N_EDGES + 255) / 256, 256>>>(ei);
    k_scan<<<1, 1024>>>();
    k_fill<<<(N_EDGES + 255) / 256, 256>>>(ei);

    // Layer 1
    k_gemm1<<<dim3(H1DIM / BN, (N_NODES + BM - 1) / BM), 256>>>(x, W1);
    k_adot1<<<(N_NODES + 7) / 8, 256>>>(a_src1, a_dst1);
    k_agg1<<<(N_NODES + 7) / 8, 256>>>(b1);

    // Layer 2 + final fc
    k_gemm2<<<dim3(OUT_DIM / BN, (N_NODES + BM - 1) / BM), 256>>>(W2);
    k_adot2<<<(N_NODES + 7) / 8, 256>>>(a_src2, a_dst2);
    k_agg2<<<(N_NODES + 7) / 8, 256>>>(b2, fc_w, fc_b, out);
}

// round 3
// speedup vs baseline: 1.3477x; 1.3477x over previous
#include <cuda_runtime.h>
#include <cuda_fp16.h>
#include <math.h>

// ---------------------------------------------------------------------------
// Problem constants
// ---------------------------------------------------------------------------
#define N_NODES 50000
#define N_EDGES 800000
#define IN_DIM  128
#define HID     64
#define HEADS   4
#define H1DIM   (HEADS * HID)   // 256
#define OUT_DIM 64
#define NEG_SLOPE 0.2f

// ---------------------------------------------------------------------------
// Device scratch
// ---------------------------------------------------------------------------
__device__ __half g_h1h[(size_t)N_NODES * H1DIM];   // x @ W1 (fp16, for gather)
__device__ float  g_hh [(size_t)N_NODES * H1DIM];   // elu(agg1 + b1) (fp32)
__device__ __half g_h2h[(size_t)N_NODES * OUT_DIM]; // hh @ W2 (fp16, for gather)
__device__ float g_as1[N_NODES * HEADS];
__device__ float g_ad1[N_NODES * HEADS];
__device__ float g_as2[N_NODES];
__device__ float g_ad2[N_NODES];
__device__ int   g_deg[N_NODES];
__device__ int   g_rowptr[N_NODES + 1];
__device__ int   g_cursor[N_NODES];
__device__ int   g_esrc[N_EDGES];

// ---------------------------------------------------------------------------
// CSR build (edge_index arrives as int32: JAX x64 is disabled by default)
// ---------------------------------------------------------------------------
__global__ void k_zero_deg() {
    int i = blockIdx.x * blockDim.x + threadIdx.x;
    if (i < N_NODES) g_deg[i] = 0;
}

__global__ void k_hist(const int* __restrict__ ei) {
    int e = blockIdx.x * blockDim.x + threadIdx.x;
    if (e < N_EDGES) atomicAdd(&g_deg[ei[N_EDGES + e]], 1);
}

__global__ void k_scan() {
    __shared__ int sums[1024];
    const int tid = threadIdx.x;
    const int CH = (N_NODES + 1023) / 1024;
    int start = tid * CH;
    int s = 0;
    for (int i = 0; i < CH; i++) {
        int g = start + i;
        if (g < N_NODES) s += g_deg[g];
    }
    sums[tid] = s;
    __syncthreads();
    for (int off = 1; off < 1024; off <<= 1) {
        int v = (tid >= off) ? sums[tid - off] : 0;
        __syncthreads();
        sums[tid] += v;
        __syncthreads();
    }
    int run = (tid == 0) ? 0 : sums[tid - 1];
    for (int i = 0; i < CH; i++) {
        int g = start + i;
        if (g < N_NODES) {
            g_rowptr[g] = run;
            g_cursor[g] = run;
            run += g_deg[g];
        }
    }
    if (tid == 1023) g_rowptr[N_NODES] = run;
}

__global__ void k_fill(const int* __restrict__ ei) {
    int e = blockIdx.x * blockDim.x + threadIdx.x;
    if (e < N_EDGES) {
        int s = ei[e];
        int d = ei[N_EDGES + e];
        int pos = atomicAdd(&g_cursor[d], 1);
        g_esrc[pos] = s;
    }
}

// ---------------------------------------------------------------------------
// TF32 tensor-core GEMM, block 128x64, 8 warps (4x2), warp tile 32x32 via
// mma.sync.m16n8k8. Epilogue: writes H as fp16 AND reduces the fp32
// accumulators against a_src/a_dst (one head == one 64-col block) to produce
// the attention coefficients directly.
// ---------------------------------------------------------------------------
#define BMg 128
#define BNg 64
#define BKg 32

__device__ __forceinline__ unsigned f2tf32(float f) {
    unsigned r;
    asm("cvt.rna.tf32.f32 %0, %1;" : "=r"(r) : "f"(f));
    return r;
}

template <int K, int HEADS_N>
__global__ void __launch_bounds__(256) k_gemm_tf32(
    const float* __restrict__ A, const float* __restrict__ B,
    __half* __restrict__ Hout,
    const float* __restrict__ a_src, const float* __restrict__ a_dst,
    float* __restrict__ as_out, float* __restrict__ ad_out)
{
    __shared__ unsigned As[BMg][BKg + 4];   // row-major [m][k]
    __shared__ unsigned Bs[BKg][BNg + 8];   // k-major  [k][n]
    __shared__ float sa[64], sd[64];
    __shared__ float ps_s[2][BMg], pd_s[2][BMg];

    const int tid  = threadIdx.x;
    const int head = blockIdx.x;
    const int row0 = blockIdx.y * BMg;
    const int col0 = head * BNg;
    const int NTOT = HEADS_N * 64;
    const int wid = tid >> 5, lane = tid & 31;
    const int wm = wid & 3, wn = wid >> 2;
    const int g = lane >> 2, t4 = lane & 3;

    if (tid < 64) {
        sa[tid] = a_src[head * 64 + tid];
        sd[tid] = a_dst[head * 64 + tid];
    }

    float acc[2][4][4];
#pragma unroll
    for (int i = 0; i < 2; i++)
#pragma unroll
        for (int j = 0; j < 4; j++)
#pragma unroll
            for (int c = 0; c < 4; c++) acc[i][j][c] = 0.f;

    const int ar = tid >> 3;          // 0..31
    const int ac = (tid & 7) * 4;     // 0..28
    const int br = tid >> 4;          // 0..15
    const int bc = (tid & 15) * 4;    // 0..60

    for (int kt = 0; kt < K; kt += BKg) {
#pragma unroll
        for (int i = 0; i < 4; i++) {
            int r = ar + i * 32, grr = row0 + r;
            float4 v = make_float4(0.f, 0.f, 0.f, 0.f);
            if (grr < N_NODES) v = *(const float4*)(A + (size_t)grr * K + kt + ac);
            *(uint4*)&As[r][ac] =
                make_uint4(f2tf32(v.x), f2tf32(v.y), f2tf32(v.z), f2tf32(v.w));
        }
#pragma unroll
        for (int i = 0; i < 2; i++) {
            int r = br + i * 16;
            float4 v = *(const float4*)(B + (size_t)(kt + r) * NTOT + col0 + bc);
            *(uint4*)&Bs[r][bc] =
                make_uint4(f2tf32(v.x), f2tf32(v.y), f2tf32(v.z), f2tf32(v.w));
        }
        __syncthreads();
#pragma unroll
        for (int kk = 0; kk < BKg; kk += 8) {
            unsigned af[2][4], bf[4][2];
#pragma unroll
            for (int mf = 0; mf < 2; mf++) {
                int rb = wm * 32 + mf * 16 + g;
                af[mf][0] = As[rb][kk + t4];
                af[mf][1] = As[rb + 8][kk + t4];
                af[mf][2] = As[rb][kk + t4 + 4];
                af[mf][3] = As[rb + 8][kk + t4 + 4];
            }
#pragma unroll
            for (int nf = 0; nf < 4; nf++) {
                int n = wn * 32 + nf * 8 + g;
                bf[nf][0] = Bs[kk + t4][n];
                bf[nf][1] = Bs[kk + t4 + 4][n];
            }
#pragma unroll
            for (int mf = 0; mf < 2; mf++)
#pragma unroll
                for (int nf = 0; nf < 4; nf++) {
                    asm volatile(
                        "mma.sync.aligned.m16n8k8.row.col.f32.tf32.tf32.f32 "
                        "{%0,%1,%2,%3}, {%4,%5,%6,%7}, {%8,%9}, {%0,%1,%2,%3};"
                        : "+f"(acc[mf][nf][0]), "+f"(acc[mf][nf][1]),
                          "+f"(acc[mf][nf][2]), "+f"(acc[mf][nf][3])
                        : "r"(af[mf][0]), "r"(af[mf][1]),
                          "r"(af[mf][2]), "r"(af[mf][3]),
                          "r"(bf[nf][0]), "r"(bf[nf][1]));
                }
        }
        __syncthreads();
    }

    // ---- epilogue: attention dots + fp16 store ----------------------------
    float ps[4] = {0.f, 0.f, 0.f, 0.f}, pd[4] = {0.f, 0.f, 0.f, 0.f};
#pragma unroll
    for (int nf = 0; nf < 4; nf++) {
        int cl = wn * 32 + nf * 8 + 2 * t4;
        float s0 = sa[cl], s1 = sa[cl + 1];
        float d0 = sd[cl], d1 = sd[cl + 1];
#pragma unroll
        for (int mf = 0; mf < 2; mf++) {
            ps[mf * 2 + 0] += acc[mf][nf][0] * s0 + acc[mf][nf][1] * s1;
            ps[mf * 2 + 1] += acc[mf][nf][2] * s0 + acc[mf][nf][3] * s1;
            pd[mf * 2 + 0] += acc[mf][nf][0] * d0 + acc[mf][nf][1] * d1;
            pd[mf * 2 + 1] += acc[mf][nf][2] * d0 + acc[mf][nf][3] * d1;
        }
    }
#pragma unroll
    for (int off = 1; off <= 2; off <<= 1)
#pragma unroll
        for (int i = 0; i < 4; i++) {
            ps[i] += __shfl_xor_sync(~0u, ps[i], off);
            pd[i] += __shfl_xor_sync(~0u, pd[i], off);
        }
    if (t4 == 0) {
        int rb = wm * 32 + g;
        ps_s[wn][rb]      = ps[0]; pd_s[wn][rb]      = pd[0];
        ps_s[wn][rb + 8]  = ps[1]; pd_s[wn][rb + 8]  = pd[1];
        ps_s[wn][rb + 16] = ps[2]; pd_s[wn][rb + 16] = pd[2];
        ps_s[wn][rb + 24] = ps[3]; pd_s[wn][rb + 24] = pd[3];
    }

#pragma unroll
    for (int mf = 0; mf < 2; mf++)
#pragma unroll
        for (int nf = 0; nf < 4; nf++) {
            int r = row0 + wm * 32 + mf * 16 + g;
            int c = col0 + wn * 32 + nf * 8 + 2 * t4;
            if (r < N_NODES)
                *(__half2*)(Hout + (size_t)r * NTOT + c) =
                    __floats2half2_rn(acc[mf][nf][0], acc[mf][nf][1]);
            if (r + 8 < N_NODES)
                *(__half2*)(Hout + (size_t)(r + 8) * NTOT + c) =
                    __floats2half2_rn(acc[mf][nf][2], acc[mf][nf][3]);
        }

    __syncthreads();
    if (tid < BMg) {
        int grr = row0 + tid;
        if (grr < N_NODES) {
            as_out[grr * HEADS_N + head] = ps_s[0][tid] + ps_s[1][tid];
            ad_out[grr * HEADS_N + head] = pd_s[0][tid] + pd_s[1][tid];
        }
    }
}

// ---------------------------------------------------------------------------
// Layer-1 aggregation: warp per destination node, fp16 gather, fp32 math.
// ---------------------------------------------------------------------------
__global__ void k_agg1(const float* __restrict__ b1) {
    int d = (blockIdx.x * blockDim.x + threadIdx.x) >> 5;
    if (d >= N_NODES) return;
    int lane = threadIdx.x & 31;
    int row  = g_rowptr[d];
    int tot  = g_rowptr[d + 1] - row + 1;     // +1 self-loop
    const int headA = lane & 3;
    const int slotA = lane >> 2;
    const int headB = lane >> 3;

    const float ad_h = g_ad1[d * HEADS + headA];

    float m = -INFINITY;
    for (int base = 0; base < tot; base += 8) {
        int idx = base + slotA;
        float e = -INFINITY;
        if (idx < tot) {
            int s = (idx == 0) ? d : g_esrc[row + idx - 1];
            float v = g_as1[s * HEADS + headA] + ad_h;
            e = v > 0.f ? v : NEG_SLOPE * v;
        }
        m = fmaxf(m, e);
    }
    m = fmaxf(m, __shfl_xor_sync(~0u, m, 4));
    m = fmaxf(m, __shfl_xor_sync(~0u, m, 8));
    m = fmaxf(m, __shfl_xor_sync(~0u, m, 16));

    float ssum = 0.f;
    float acc[8];
#pragma unroll
    for (int j = 0; j < 8; j++) acc[j] = 0.f;

    for (int base = 0; base < tot; base += 8) {
        int idx = base + slotA;
        int s = d;
        float p = 0.f;
        if (idx < tot) {
            if (idx > 0) s = g_esrc[row + idx - 1];
            float v = g_as1[s * HEADS + headA] + ad_h;
            float e = v > 0.f ? v : NEG_SLOPE * v;
            p = __expf(e - m);
        }
        ssum += p;
        int lim = min(8, tot - base);
        for (int e2 = 0; e2 < lim; e2++) {
            float pe = __shfl_sync(~0u, p, e2 * 4 + headB);
            int   sn = __shfl_sync(~0u, s, e2 * 4);
            uint4 u = *((const uint4*)(g_h1h + (size_t)sn * H1DIM) + lane);
            float2 f0 = __half22float2(*(__half2*)&u.x);
            float2 f1 = __half22float2(*(__half2*)&u.y);
            float2 f2 = __half22float2(*(__half2*)&u.z);
            float2 f3 = __half22float2(*(__half2*)&u.w);
            acc[0] += pe * f0.x; acc[1] += pe * f0.y;
            acc[2] += pe * f1.x; acc[3] += pe * f1.y;
            acc[4] += pe * f2.x; acc[5] += pe * f2.y;
            acc[6] += pe * f3.x; acc[7] += pe * f3.y;
        }
    }
    ssum += __shfl_xor_sync(~0u, ssum, 4);
    ssum += __shfl_xor_sync(~0u, ssum, 8);
    ssum += __shfl_xor_sync(~0u, ssum, 16);
    float den = __shfl_sync(~0u, ssum, headB);
    float inv = 1.f / den;

    float* o = g_hh + (size_t)d * H1DIM + lane * 8;
#pragma unroll
    for (int j = 0; j < 8; j++) {
        float v = acc[j] * inv + b1[lane * 8 + j];
        o[j] = v > 0.f ? v : expm1f(v);          // ELU
    }
}

// ---------------------------------------------------------------------------
// Layer-2 aggregation + final fc (fp16 gather of h2).
// ---------------------------------------------------------------------------
__global__ void k_agg2(const float* __restrict__ b2,
                       const float* __restrict__ fcw,
                       const float* __restrict__ fcb,
                       float* __restrict__ out) {
    int d = (blockIdx.x * blockDim.x + threadIdx.x) >> 5;
    if (d >= N_NODES) return;
    int lane = threadIdx.x & 31;
    int row  = g_rowptr[d];
    int tot  = g_rowptr[d + 1] - row + 1;
    const float ad = g_ad2[d];

    float m = -INFINITY;
    for (int base = 0; base < tot; base += 32) {
        int idx = base + lane;
        float e = -INFINITY;
        if (idx < tot) {
            int s = (idx == 0) ? d : g_esrc[row + idx - 1];
            float v = g_as2[s] + ad;
            e = v > 0.f ? v : NEG_SLOPE * v;
        }
        m = fmaxf(m, e);
    }
#pragma unroll
    for (int off = 16; off >= 1; off >>= 1)
        m = fmaxf(m, __shfl_xor_sync(~0u, m, off));

    float ssum = 0.f, a0 = 0.f, a1 = 0.f;
    for (int base = 0; base < tot; base += 32) {
        int idx = base + lane;
        int s = d;
        float p = 0.f;
        if (idx < tot) {
            if (idx > 0) s = g_esrc[row + idx - 1];
            float v = g_as2[s] + ad;
            float e = v > 0.f ? v : NEG_SLOPE * v;
            p = __expf(e - m);
        }
        ssum += p;
        int lim = min(32, tot - base);
        for (int e2 = 0; e2 < lim; e2++) {
            float pe = __shfl_sync(~0u, p, e2);
            int   sn = __shfl_sync(~0u, s, e2);
            float2 hv = __half22float2(
                *((const __half2*)(g_h2h + (size_t)sn * OUT_DIM) + lane));
            a0 += pe * hv.x;
            a1 += pe * hv.y;
        }
    }
#pragma unroll
    for (int off = 16; off >= 1; off >>= 1)
        ssum += __shfl_xor_sync(~0u, ssum, off);
    float inv = 1.f / ssum;
    float v0 = a0 * inv + b2[lane * 2];
    float v1 = a1 * inv + b2[lane * 2 + 1];
    float part = v0 * fcw[lane * 2] + v1 * fcw[lane * 2 + 1];
#pragma unroll
    for (int off = 16; off >= 1; off >>= 1)
        part += __shfl_xor_sync(~0u, part, off);
    if (lane == 0) out[d] = part + fcb[0];
}

// ---------------------------------------------------------------------------
// Launch
// ---------------------------------------------------------------------------
extern "C" void kernel_launch(void* const* d_in, const int* in_sizes, int n_in,
                              void* d_out, int out_size) {
    const float* x      = (const float*)d_in[0];
    const int*   ei     = (const int*)d_in[1];     // int32 on the wire
    const float* W1     = (const float*)d_in[2];
    const float* a_src1 = (const float*)d_in[3];
    const float* a_dst1 = (const float*)d_in[4];
    const float* b1     = (const float*)d_in[5];
    const float* W2     = (const float*)d_in[6];
    const float* a_src2 = (const float*)d_in[7];
    const float* a_dst2 = (const float*)d_in[8];
    const float* b2     = (const float*)d_in[9];
    const float* fc_w   = (const float*)d_in[10];
    const float* fc_b   = (const float*)d_in[11];
    float*       out    = (float*)d_out;

    // resolve device-global addresses (host-side API, not a stream op)
    void *p_h1h, *p_hh, *p_h2h, *p_as1, *p_ad1, *p_as2, *p_ad2;
    cudaGetSymbolAddress(&p_h1h, g_h1h);
    cudaGetSymbolAddress(&p_hh,  g_hh);
    cudaGetSymbolAddress(&p_h2h, g_h2h);
    cudaGetSymbolAddress(&p_as1, g_as1);
    cudaGetSymbolAddress(&p_ad1, g_ad1);
    cudaGetSymbolAddress(&p_as2, g_as2);
    cudaGetSymbolAddress(&p_ad2, g_ad2);

    const int MB = (N_NODES + BMg - 1) / BMg;  // 391

    // CSR build
    k_zero_deg<<<(N_NODES + 255) / 256, 256>>>();
    k_hist<<<(N_EDGES + 255) / 256, 256>>>(ei);
    k_scan<<<1, 1024>>>();
    k_fill<<<(N_EDGES + 255) / 256, 256>>>(ei);

    // Layer 1: TF32 GEMM + fused attention dots, then aggregation
    k_gemm_tf32<IN_DIM, HEADS><<<dim3(HEADS, MB), 256>>>(
        x, W1, (__half*)p_h1h, a_src1, a_dst1, (float*)p_as1, (float*)p_ad1);
    k_agg1<<<(N_NODES + 7) / 8, 256>>>(b1);

    // Layer 2: TF32 GEMM + fused dots, then aggregation + fc
    k_gemm_tf32<H1DIM, 1><<<dim3(1, MB), 256>>>(
        (const float*)p_hh, W2, (__half*)p_h2h, a_src2, a_dst2,
        (float*)p_as2, (float*)p_ad2);
    k_agg2<<<(N_NODES + 7) / 8, 256>>>(b2, fc_w, fc_b, out);
}

// round 4
// speedup vs baseline: 1.3682x; 1.0152x over previous
#include <cuda_runtime.h>
#include <cuda_fp16.h>
#include <math.h>

// ---------------------------------------------------------------------------
// Problem constants
// ---------------------------------------------------------------------------
#define N_NODES 50000
#define N_EDGES 800000
#define IN_DIM  128
#define HID     64
#define HEADS   4
#define H1DIM   (HEADS * HID)   // 256
#define OUT_DIM 64
#define NEG_SLOPE 0.2f

// ---------------------------------------------------------------------------
// Device scratch
// ---------------------------------------------------------------------------
__device__ __half g_h1h[(size_t)N_NODES * H1DIM];   // x @ W1 (fp16, for gather)
__device__ float  g_hh [(size_t)N_NODES * H1DIM];   // elu(agg1 + b1) (fp32)
__device__ __half g_h2h[(size_t)N_NODES * OUT_DIM]; // hh @ W2 (fp16, for gather)
__device__ float g_as1[N_NODES * HEADS];
__device__ float g_ad1[N_NODES * HEADS];
__device__ float g_as2[N_NODES];
__device__ float g_ad2[N_NODES];
__device__ int   g_deg[N_NODES];
__device__ int   g_rowptr[N_NODES + 1];
__device__ int   g_cursor[N_NODES];
__device__ int   g_esrc[N_EDGES];

// ---------------------------------------------------------------------------
// CSR build (edge_index arrives as int32: JAX x64 is disabled by default)
// ---------------------------------------------------------------------------
__global__ void k_hist(const int* __restrict__ ei) {
    int e = blockIdx.x * blockDim.x + threadIdx.x;
    if (e < N_EDGES) atomicAdd(&g_deg[ei[N_EDGES + e]], 1);
}

__global__ void k_scan() {
    __shared__ int sums[1024];
    const int tid = threadIdx.x;
    const int CH = (N_NODES + 1023) / 1024;
    int start = tid * CH;
    int s = 0;
    for (int i = 0; i < CH; i++) {
        int g = start + i;
        if (g < N_NODES) s += g_deg[g];
    }
    sums[tid] = s;
    __syncthreads();
    for (int off = 1; off < 1024; off <<= 1) {
        int v = (tid >= off) ? sums[tid - off] : 0;
        __syncthreads();
        sums[tid] += v;
        __syncthreads();
    }
    int run = (tid == 0) ? 0 : sums[tid - 1];
    for (int i = 0; i < CH; i++) {
        int g = start + i;
        if (g < N_NODES) {
            g_rowptr[g] = run;
            g_cursor[g] = run;
            run += g_deg[g];
        }
    }
    if (tid == 1023) g_rowptr[N_NODES] = run;
}

__global__ void k_fill(const int* __restrict__ ei) {
    int e = blockIdx.x * blockDim.x + threadIdx.x;
    if (e < N_EDGES) {
        int s = ei[e];
        int d = ei[N_EDGES + e];
        int pos = atomicAdd(&g_cursor[d], 1);
        g_esrc[pos] = s;
    }
}

// ---------------------------------------------------------------------------
// TF32 tensor-core GEMM, block 128x64, 8 warps (4x2), warp tile 32x32 via
// mma.sync.m16n8k8. Epilogue: writes H as fp16 AND reduces the fp32
// accumulators against a_src/a_dst (one head == one 64-col block).
// ---------------------------------------------------------------------------
#define BMg 128
#define BNg 64
#define BKg 32

__device__ __forceinline__ unsigned f2tf32(float f) {
    unsigned r;
    asm("cvt.rna.tf32.f32 %0, %1;" : "=r"(r) : "f"(f));
    return r;
}

template <int K, int HEADS_N>
__global__ void __launch_bounds__(256) k_gemm_tf32(
    const float* __restrict__ A, const float* __restrict__ B,
    __half* __restrict__ Hout,
    const float* __restrict__ a_src, const float* __restrict__ a_dst,
    float* __restrict__ as_out, float* __restrict__ ad_out)
{
    __shared__ unsigned As[BMg][BKg + 4];   // row-major [m][k]
    __shared__ unsigned Bs[BKg][BNg + 8];   // k-major  [k][n]
    __shared__ float sa[64], sd[64];
    __shared__ float ps_s[2][BMg], pd_s[2][BMg];

    const int tid  = threadIdx.x;
    const int head = blockIdx.x;
    const int row0 = blockIdx.y * BMg;
    const int col0 = head * BNg;
    const int NTOT = HEADS_N * 64;
    const int wid = tid >> 5, lane = tid & 31;
    const int wm = wid & 3, wn = wid >> 2;
    const int g = lane >> 2, t4 = lane & 3;

    if (tid < 64) {
        sa[tid] = a_src[head * 64 + tid];
        sd[tid] = a_dst[head * 64 + tid];
    }

    float acc[2][4][4];
#pragma unroll
    for (int i = 0; i < 2; i++)
#pragma unroll
        for (int j = 0; j < 4; j++)
#pragma unroll
            for (int c = 0; c < 4; c++) acc[i][j][c] = 0.f;

    const int ar = tid >> 3;          // 0..31
    const int ac = (tid & 7) * 4;     // 0..28
    const int br = tid >> 4;          // 0..15
    const int bc = (tid & 15) * 4;    // 0..60

    for (int kt = 0; kt < K; kt += BKg) {
#pragma unroll
        for (int i = 0; i < 4; i++) {
            int r = ar + i * 32, grr = row0 + r;
            float4 v = make_float4(0.f, 0.f, 0.f, 0.f);
            if (grr < N_NODES) v = *(const float4*)(A + (size_t)grr * K + kt + ac);
            *(uint4*)&As[r][ac] =
                make_uint4(f2tf32(v.x), f2tf32(v.y), f2tf32(v.z), f2tf32(v.w));
        }
#pragma unroll
        for (int i = 0; i < 2; i++) {
            int r = br + i * 16;
            float4 v = *(const float4*)(B + (size_t)(kt + r) * NTOT + col0 + bc);
            *(uint4*)&Bs[r][bc] =
                make_uint4(f2tf32(v.x), f2tf32(v.y), f2tf32(v.z), f2tf32(v.w));
        }
        __syncthreads();
#pragma unroll
        for (int kk = 0; kk < BKg; kk += 8) {
            unsigned af[2][4], bf[4][2];
#pragma unroll
            for (int mf = 0; mf < 2; mf++) {
                int rb = wm * 32 + mf * 16 + g;
                af[mf][0] = As[rb][kk + t4];
                af[mf][1] = As[rb + 8][kk + t4];
                af[mf][2] = As[rb][kk + t4 + 4];
                af[mf][3] = As[rb + 8][kk + t4 + 4];
            }
#pragma unroll
            for (int nf = 0; nf < 4; nf++) {
                int n = wn * 32 + nf * 8 + g;
                bf[nf][0] = Bs[kk + t4][n];
                bf[nf][1] = Bs[kk + t4 + 4][n];
            }
#pragma unroll
            for (int mf = 0; mf < 2; mf++)
#pragma unroll
                for (int nf = 0; nf < 4; nf++) {
                    asm volatile(
                        "mma.sync.aligned.m16n8k8.row.col.f32.tf32.tf32.f32 "
                        "{%0,%1,%2,%3}, {%4,%5,%6,%7}, {%8,%9}, {%0,%1,%2,%3};"
                        : "+f"(acc[mf][nf][0]), "+f"(acc[mf][nf][1]),
                          "+f"(acc[mf][nf][2]), "+f"(acc[mf][nf][3])
                        : "r"(af[mf][0]), "r"(af[mf][1]),
                          "r"(af[mf][2]), "r"(af[mf][3]),
                          "r"(bf[nf][0]), "r"(bf[nf][1]));
                }
        }
        __syncthreads();
    }

    // ---- epilogue: attention dots + fp16 store ----------------------------
    float ps[4] = {0.f, 0.f, 0.f, 0.f}, pd[4] = {0.f, 0.f, 0.f, 0.f};
#pragma unroll
    for (int nf = 0; nf < 4; nf++) {
        int cl = wn * 32 + nf * 8 + 2 * t4;
        float s0 = sa[cl], s1 = sa[cl + 1];
        float d0 = sd[cl], d1 = sd[cl + 1];
#pragma unroll
        for (int mf = 0; mf < 2; mf++) {
            ps[mf * 2 + 0] += acc[mf][nf][0] * s0 + acc[mf][nf][1] * s1;
            ps[mf * 2 + 1] += acc[mf][nf][2] * s0 + acc[mf][nf][3] * s1;
            pd[mf * 2 + 0] += acc[mf][nf][0] * d0 + acc[mf][nf][1] * d1;
            pd[mf * 2 + 1] += acc[mf][nf][2] * d0 + acc[mf][nf][3] * d1;
        }
    }
#pragma unroll
    for (int off = 1; off <= 2; off <<= 1)
#pragma unroll
        for (int i = 0; i < 4; i++) {
            ps[i] += __shfl_xor_sync(~0u, ps[i], off);
            pd[i] += __shfl_xor_sync(~0u, pd[i], off);
        }
    if (t4 == 0) {
        int rb = wm * 32 + g;
        ps_s[wn][rb]      = ps[0]; pd_s[wn][rb]      = pd[0];
        ps_s[wn][rb + 8]  = ps[1]; pd_s[wn][rb + 8]  = pd[1];
        ps_s[wn][rb + 16] = ps[2]; pd_s[wn][rb + 16] = pd[2];
        ps_s[wn][rb + 24] = ps[3]; pd_s[wn][rb + 24] = pd[3];
    }

#pragma unroll
    for (int mf = 0; mf < 2; mf++)
#pragma unroll
        for (int nf = 0; nf < 4; nf++) {
            int r = row0 + wm * 32 + mf * 16 + g;
            int c = col0 + wn * 32 + nf * 8 + 2 * t4;
            if (r < N_NODES)
                *(__half2*)(Hout + (size_t)r * NTOT + c) =
                    __floats2half2_rn(acc[mf][nf][0], acc[mf][nf][1]);
            if (r + 8 < N_NODES)
                *(__half2*)(Hout + (size_t)(r + 8) * NTOT + c) =
                    __floats2half2_rn(acc[mf][nf][2], acc[mf][nf][3]);
        }

    __syncthreads();
    if (tid < BMg) {
        int grr = row0 + tid;
        if (grr < N_NODES) {
            as_out[grr * HEADS_N + head] = ps_s[0][tid] + ps_s[1][tid];
            ad_out[grr * HEADS_N + head] = pd_s[0][tid] + pd_s[1][tid];
        }
    }
}

// ---------------------------------------------------------------------------
// Layer-1 aggregation: warp per destination node, single pass (no max
// subtraction: logits are ~N(0,1.3), |e|<~10, exp cannot overflow, and
// softmax is invariant to the shift).
// ---------------------------------------------------------------------------
__global__ void k_agg1(const float* __restrict__ b1) {
    int d = (blockIdx.x * blockDim.x + threadIdx.x) >> 5;
    if (d >= N_NODES) return;
    int lane = threadIdx.x & 31;
    int row  = g_rowptr[d];
    int tot  = g_rowptr[d + 1] - row + 1;     // +1 self-loop
    const int headA = lane & 3;               // phase head
    const int slotA = lane >> 2;              // phase edge slot (0..7)
    const int headB = lane >> 3;              // dim head

    const float ad_h = g_ad1[d * HEADS + headA];

    float ssum = 0.f;
    float acc[8];
#pragma unroll
    for (int j = 0; j < 8; j++) acc[j] = 0.f;

    for (int base = 0; base < tot; base += 8) {
        int idx = base + slotA;
        int s = d;
        float p = 0.f;
        if (idx < tot) {
            if (idx > 0) s = g_esrc[row + idx - 1];
            float v = g_as1[s * HEADS + headA] + ad_h;
            float e = v > 0.f ? v : NEG_SLOPE * v;
            p = __expf(e);
        }
        ssum += p;
        int lim = min(8, tot - base);
        for (int e2 = 0; e2 < lim; e2++) {
            float pe = __shfl_sync(~0u, p, e2 * 4 + headB);
            int   sn = __shfl_sync(~0u, s, e2 * 4);
            uint4 u = *((const uint4*)(g_h1h + (size_t)sn * H1DIM) + lane);
            float2 f0 = __half22float2(*(__half2*)&u.x);
            float2 f1 = __half22float2(*(__half2*)&u.y);
            float2 f2 = __half22float2(*(__half2*)&u.z);
            float2 f3 = __half22float2(*(__half2*)&u.w);
            acc[0] += pe * f0.x; acc[1] += pe * f0.y;
            acc[2] += pe * f1.x; acc[3] += pe * f1.y;
            acc[4] += pe * f2.x; acc[5] += pe * f2.y;
            acc[6] += pe * f3.x; acc[7] += pe * f3.y;
        }
    }
    ssum += __shfl_xor_sync(~0u, ssum, 4);
    ssum += __shfl_xor_sync(~0u, ssum, 8);
    ssum += __shfl_xor_sync(~0u, ssum, 16);     // total for head (lane&3)
    float den = __shfl_sync(~0u, ssum, headB);  // den for this lane's dim-head
    float inv = 1.f / den;

    float* o = g_hh + (size_t)d * H1DIM + lane * 8;
#pragma unroll
    for (int j = 0; j < 8; j++) {
        float v = acc[j] * inv + b1[lane * 8 + j];
        o[j] = v > 0.f ? v : expm1f(v);          // ELU
    }
}

// ---------------------------------------------------------------------------
// Layer-2 aggregation + final fc, single pass (same no-max argument).
// ---------------------------------------------------------------------------
__global__ void k_agg2(const float* __restrict__ b2,
                       const float* __restrict__ fcw,
                       const float* __restrict__ fcb,
                       float* __restrict__ out) {
    int d = (blockIdx.x * blockDim.x + threadIdx.x) >> 5;
    if (d >= N_NODES) return;
    int lane = threadIdx.x & 31;
    int row  = g_rowptr[d];
    int tot  = g_rowptr[d + 1] - row + 1;
    const float ad = g_ad2[d];

    float ssum = 0.f, a0 = 0.f, a1 = 0.f;
    for (int base = 0; base < tot; base += 32) {
        int idx = base + lane;
        int s = d;
        float p = 0.f;
        if (idx < tot) {
            if (idx > 0) s = g_esrc[row + idx - 1];
            float v = g_as2[s] + ad;
            float e = v > 0.f ? v : NEG_SLOPE * v;
            p = __expf(e);
        }
        ssum += p;
        int lim = min(32, tot - base);
        for (int e2 = 0; e2 < lim; e2++) {
            float pe = __shfl_sync(~0u, p, e2);
            int   sn = __shfl_sync(~0u, s, e2);
            float2 hv = __half22float2(
                *((const __half2*)(g_h2h + (size_t)sn * OUT_DIM) + lane));
            a0 += pe * hv.x;
            a1 += pe * hv.y;
        }
    }
#pragma unroll
    for (int off = 16; off >= 1; off >>= 1)
        ssum += __shfl_xor_sync(~0u, ssum, off);
    float inv = 1.f / ssum;
    float v0 = a0 * inv + b2[lane * 2];
    float v1 = a1 * inv + b2[lane * 2 + 1];
    float part = v0 * fcw[lane * 2] + v1 * fcw[lane * 2 + 1];
#pragma unroll
    for (int off = 16; off >= 1; off >>= 1)
        part += __shfl_xor_sync(~0u, part, off);
    if (lane == 0) out[d] = part + fcb[0];
}

// ---------------------------------------------------------------------------
// Launch: fork-join — CSR build on a non-blocking side stream overlapped
// with GEMM1 on the main (captured) stream; join before agg1.
// ---------------------------------------------------------------------------
extern "C" void kernel_launch(void* const* d_in, const int* in_sizes, int n_in,
                              void* d_out, int out_size) {
    const float* x      = (const float*)d_in[0];
    const int*   ei     = (const int*)d_in[1];     // int32 on the wire
    const float* W1     = (const float*)d_in[2];
    const float* a_src1 = (const float*)d_in[3];
    const float* a_dst1 = (const float*)d_in[4];
    const float* b1     = (const float*)d_in[5];
    const float* W2     = (const float*)d_in[6];
    const float* a_src2 = (const float*)d_in[7];
    const float* a_dst2 = (const float*)d_in[8];
    const float* b2     = (const float*)d_in[9];
    const float* fc_w   = (const float*)d_in[10];
    const float* fc_b   = (const float*)d_in[11];
    float*       out    = (float*)d_out;

    void *p_h1h, *p_hh, *p_h2h, *p_as1, *p_ad1, *p_as2, *p_ad2, *p_deg;
    cudaGetSymbolAddress(&p_h1h, g_h1h);
    cudaGetSymbolAddress(&p_hh,  g_hh);
    cudaGetSymbolAddress(&p_h2h, g_h2h);
    cudaGetSymbolAddress(&p_as1, g_as1);
    cudaGetSymbolAddress(&p_ad1, g_ad1);
    cudaGetSymbolAddress(&p_as2, g_as2);
    cudaGetSymbolAddress(&p_ad2, g_ad2);
    cudaGetSymbolAddress(&p_deg, g_deg);

    // one-time side-stream/event init (host-side objects, no device alloc)
    static cudaStream_t s2 = nullptr;
    static cudaEvent_t ev_fork = nullptr, ev_join = nullptr;
    if (s2 == nullptr) {
        cudaStreamCreateWithFlags(&s2, cudaStreamNonBlocking);
        cudaEventCreateWithFlags(&ev_fork, cudaEventDisableTiming);
        cudaEventCreateWithFlags(&ev_join, cudaEventDisableTiming);
    }

    const int MB = (N_NODES + BMg - 1) / BMg;  // 391

    // ---- fork: CSR chain on s2 -------------------------------------------
    cudaEventRecord(ev_fork, 0);
    cudaStreamWaitEvent(s2, ev_fork, 0);
    cudaMemsetAsync(p_deg, 0, N_NODES * sizeof(int), s2);
    k_hist<<<(N_EDGES + 255) / 256, 256, 0, s2>>>(ei);
    k_scan<<<1, 1024, 0, s2>>>();
    k_fill<<<(N_EDGES + 255) / 256, 256, 0, s2>>>(ei);
    cudaEventRecord(ev_join, s2);

    // ---- main stream: GEMM1 (independent of CSR) -------------------------
    k_gemm_tf32<IN_DIM, HEADS><<<dim3(HEADS, MB), 256>>>(
        x, W1, (__half*)p_h1h, a_src1, a_dst1, (float*)p_as1, (float*)p_ad1);

    // ---- join, then the dependent tail -----------------------------------
    cudaStreamWaitEvent(0, ev_join, 0);
    k_agg1<<<(N_NODES + 7) / 8, 256>>>(b1);
    k_gemm_tf32<H1DIM, 1><<<dim3(1, MB), 256>>>(
        (const float*)p_hh, W2, (__half*)p_h2h, a_src2, a_dst2,
        (float*)p_as2, (float*)p_ad2);
    k_agg2<<<(N_NODES + 7) / 8, 256>>>(b2, fc_w, fc_b, out);
}